// round 8
// baseline (speedup 1.0000x reference)
#include <cuda_runtime.h>
#include <cstdint>

#define BATCH 32
#define CIN   256
#define COUT  256
#define HH_   56
#define WW_   56
#define HW_   (HH_*WW_)
#define NPOS  (BATCH*HW_)

// ---------------- device scratch ----------------
__device__ uint4 g_xpack[NPOS * 2];        // [pos][2]: 8 u32 sign bits (bit=1 iff x>=0)
__device__ uint4 g_wpack[COUT * 9 * 2];    // [cout*9+tap][2]

// ---------------- fused pack kernel ----------------
__global__ void pack_all_kernel(const float* __restrict__ x,
                                const float* __restrict__ wgt) {
    if (blockIdx.x < 392) {                       // 392*256 == NPOS exactly
        int pos = blockIdx.x * 256 + threadIdx.x;
        int b  = pos / HW_;
        int hw = pos - b * HW_;
        const float* xp = x + (size_t)b * CIN * HW_ + hw;
        uint32_t wds[8];
        #pragma unroll
        for (int k = 0; k < 8; ++k) {
            uint32_t wd = 0;
            #pragma unroll
            for (int i = 0; i < 32; ++i) {
                float v = xp[(size_t)(k * 32 + i) * HW_];
                wd |= (v >= 0.0f ? 1u : 0u) << i;
            }
            wds[k] = wd;
        }
        g_xpack[pos * 2 + 0] = make_uint4(wds[0], wds[1], wds[2], wds[3]);
        g_xpack[pos * 2 + 1] = make_uint4(wds[4], wds[5], wds[6], wds[7]);
    } else {
        int idx = (blockIdx.x - 392) * 256 + threadIdx.x;   // cout*9+tap
        if (idx >= COUT * 9) return;
        int cout = idx / 9;
        int tap  = idx - cout * 9;
        const float* wp = wgt + (size_t)cout * CIN * 9 + tap;
        uint32_t wds[8];
        #pragma unroll
        for (int k = 0; k < 8; ++k) {
            uint32_t wd = 0;
            #pragma unroll
            for (int i = 0; i < 32; ++i) {
                float v = wp[(size_t)(k * 32 + i) * 9];
                wd |= (v >= 0.0f ? 1u : 0u) << i;
            }
            wds[k] = wd;
        }
        g_wpack[idx * 2 + 0] = make_uint4(wds[0], wds[1], wds[2], wds[3]);
        g_wpack[idx * 2 + 1] = make_uint4(wds[4], wds[5], wds[6], wds[7]);
    }
}

// ---------------- main conv: cin split across 4 lanes + x prefetch -----------
// Block = 256 threads = 8 warps. Lane = quarter*8 + csub.
//   csub (0..7)   -> cout = bz*64 + wid*8 + csub
//   quarter (0..3)-> cin words 2q, 2q+1 (64 channels)
// Block computes one (b, h) output row for 64 couts.
__global__ void __launch_bounds__(256, 4)
bconv_pop_kernel(const float* __restrict__ bias, float* __restrict__ out) {
    __shared__ uint2 xs[3 * WW_ * 4];     // [row][v][quarter]

    const int tid     = threadIdx.x;
    const int lane    = tid & 31;
    const int wid     = tid >> 5;
    const int quarter = lane >> 3;
    const int csub    = lane & 7;
    const int h       = blockIdx.x;
    const int b       = blockIdx.y;
    const int cout    = blockIdx.z * 64 + wid * 8 + csub;

    const bool rv0 = (h > 0), rv2 = (h < HH_ - 1);

    // ---- stage x (3 rows x 56 cols x 4 quarters of uint2) ----
    const uint2* gx2 = (const uint2*)g_xpack;
    for (int i = tid; i < 3 * WW_ * 4; i += 256) {
        int row = i / (WW_ * 4);
        int rem = i - row * (WW_ * 4);
        int v = rem >> 2, q = rem & 3;
        int rin = h - 1 + row;
        uint2 val = make_uint2(0u, 0u);
        if (rin >= 0 && rin < HH_)
            val = gx2[((size_t)(b * HH_ + rin) * WW_ + v) * 4 + q];
        xs[(row * WW_ + v) * 4 + q] = val;
    }

    // ---- per-lane quarter-weights in registers (18 regs) ----
    uint32_t wreg[9][2];
    #pragma unroll
    for (int t = 0; t < 9; ++t) {
        uint2 a = ((const uint2*)g_wpack)[(cout * 9 + t) * 4 + quarter];
        wreg[t][0] = a.x; wreg[t][1] = a.y;
    }
    const float bv = bias[cout];

    // ---- per-quarter pad-correction constants (64 channels each) ----
    int pm[3], pl[3], pr[3];
    #pragma unroll
    for (int dh = 0; dh < 3; ++dh) {
        int p0 = __popc(wreg[dh * 3 + 0][0]) + __popc(wreg[dh * 3 + 0][1]);
        int p1 = __popc(wreg[dh * 3 + 1][0]) + __popc(wreg[dh * 3 + 1][1]);
        int p2 = __popc(wreg[dh * 3 + 2][0]) + __popc(wreg[dh * 3 + 2][1]);
        pm[dh] = p0 + p1 + p2; pl[dh] = p1 + p2; pr[dh] = p0 + p1;
    }
    const int nrows = (int)rv0 + 1 + (int)rv2;
    const int cmid   = 192 * nrows + 2 * ((rv0 ? 0 : pm[0]) + (rv2 ? 0 : pm[2]));
    const int cleft  = 128 * nrows + 2 * ((rv0 ? 0 : pl[0]) + (rv2 ? 0 : pl[2]));
    const int cright = 128 * nrows + 2 * ((rv0 ? 0 : pr[0]) + (rv2 ? 0 : pr[2]));

    __syncthreads();

    float* obase = out + ((size_t)(b * COUT + cout) * HH_ + h) * WW_;

    int ring[4] = {0, 0, 0, 0};
    float fb[8];

    // current-column x words (prefetched one step ahead)
    uint2 xc[3];
    #pragma unroll
    for (int r = 0; r < 3; ++r) xc[r] = xs[(r * WW_ + 0) * 4 + quarter];

    for (int v0 = 0; v0 < 7; ++v0) {
        #pragma unroll
        for (int u = 0; u < 8; ++u) {
            const int v = v0 * 8 + u;

            // prefetch column v+1 (runtime-guard only on the final step)
            uint2 xn[3];
            const bool havenext = (u < 7) || (v0 < 6);
            if (havenext) {
                #pragma unroll
                for (int r = 0; r < 3; ++r)
                    xn[r] = xs[(r * WW_ + v + 1) * 4 + quarter];
            }

            int addn = 0, addm = 0, addo = 0;
            #pragma unroll
            for (int row = 0; row < 3; ++row) {
                uint32_t x0 = xc[row].x, x1 = xc[row].y;
                addn += __popc(x0 ^ wreg[row * 3 + 0][0]) + __popc(x1 ^ wreg[row * 3 + 0][1]);
                addm += __popc(x0 ^ wreg[row * 3 + 1][0]) + __popc(x1 ^ wreg[row * 3 + 1][1]);
                addo += __popc(x0 ^ wreg[row * 3 + 2][0]) + __popc(x1 ^ wreg[row * 3 + 2][1]);
            }
            ring[(u + 1) & 3] += addn;      // w = v+1
            ring[u & 3]       += addm;      // w = v
            ring[(u + 3) & 3] += addo;      // w = v-1 (completes now)

            if (u == 0) {
                if (v0 == 0) {
                    ring[3] = 0;            // discard w=-1 garbage
                } else {
                    int comb = cmid - 2 * ring[3];
                    comb += __shfl_xor_sync(0xffffffffu, comb, 8);
                    comb += __shfl_xor_sync(0xffffffffu, comb, 16);
                    fb[7] = (float)comb + bv;
                    ring[3] = 0;
                    if (quarter == 0) {
                        *(float4*)(obase + (v0 - 1) * 8)     = make_float4(fb[0], fb[1], fb[2], fb[3]);
                        *(float4*)(obase + (v0 - 1) * 8 + 4) = make_float4(fb[4], fb[5], fb[6], fb[7]);
                    }
                }
            } else {
                const int slot = (u + 3) & 3;
                int c = cmid;
                if (u == 1) c = (v0 == 0) ? cleft : cmid;   // w==0 edge
                int comb = c - 2 * ring[slot];
                comb += __shfl_xor_sync(0xffffffffu, comb, 8);
                comb += __shfl_xor_sync(0xffffffffu, comb, 16);
                fb[(u - 1) & 7] = (float)comb + bv;
                ring[slot] = 0;
            }

            if (havenext) {
                #pragma unroll
                for (int r = 0; r < 3; ++r) xc[r] = xn[r];
            }
        }
    }
    // tail: w = 55 (edge) sits in slot 3
    {
        int comb = cright - 2 * ring[3];
        comb += __shfl_xor_sync(0xffffffffu, comb, 8);
        comb += __shfl_xor_sync(0xffffffffu, comb, 16);
        fb[7] = (float)comb + bv;
    }
    if (quarter == 0) {
        *(float4*)(obase + 48) = make_float4(fb[0], fb[1], fb[2], fb[3]);
        *(float4*)(obase + 52) = make_float4(fb[4], fb[5], fb[6], fb[7]);
    }
}

// ---------------------------------------------------------------------------
extern "C" void kernel_launch(void* const* d_in, const int* in_sizes, int n_in,
                              void* d_out, int out_size) {
    const float* x    = (const float*)d_in[0];
    const float* wgt  = (const float*)d_in[1];
    const float* bias = (const float*)d_in[2];
    float* out = (float*)d_out;

    pack_all_kernel<<<401, 256>>>(x, wgt);
    dim3 grid(HH_, BATCH, 4);
    bconv_pop_kernel<<<grid, 256>>>(bias, out);
}